// round 1
// baseline (speedup 1.0000x reference)
#include <cuda_runtime.h>

#define NB 8       // batch
#define NT 12      // time / feature-in dim
#define NN 20000   // nodes
#define NE 320000  // edges
#define NF 64      // gcn hidden

// Scratch: h = X^T W_gcn  and  agg = scatter-add accumulator. 41 MB each.
__device__ __align__(128) float g_h[(size_t)NB * NN * NF];
__device__ __align__(128) float g_agg[(size_t)NB * NN * NF];

// ---------------------------------------------------------------------------
// Kernel 1: h[b,n,f] = sum_t x[b,t,n] * w_gcn[t,f]; also zero agg.
// Block = 256 threads = 4 nodes x 64 f-lanes. x loads broadcast within warp.
// ---------------------------------------------------------------------------
__global__ void k1_xw(const float* __restrict__ x, const float* __restrict__ w_gcn) {
    __shared__ float ws[NT * NF];
    int tid = threadIdx.x;
    for (int i = tid; i < NT * NF; i += 256) ws[i] = w_gcn[i];
    __syncthreads();

    int b = blockIdx.y;
    int n = blockIdx.x * 4 + (tid >> 6);
    int f = tid & 63;

    const float* xb = x + (size_t)b * NT * NN + n;
    float acc = 0.f;
#pragma unroll
    for (int t = 0; t < NT; ++t)
        acc += xb[(size_t)t * NN] * ws[t * NF + f];

    size_t o = ((size_t)b * NN + n) * NF + f;
    g_h[o]   = acc;
    g_agg[o] = 0.f;
}

// ---------------------------------------------------------------------------
// Kernel 2: edge scatter. One thread per (b, e, quad-of-4-floats).
// agg[b,dst,4q..4q+3] += w_e * h[b,src,4q..4q+3]  via red.global.add.v4.f32.
// 16 threads per edge share src/dst/w via L1 broadcast.
// ---------------------------------------------------------------------------
__global__ void k2_scatter(const int* __restrict__ esrc, const int* __restrict__ edst,
                           const float* __restrict__ ew) {
    int idx = blockIdx.x * blockDim.x + threadIdx.x;   // covers NE*16
    int e = idx >> 4;
    int q = idx & 15;
    if (e >= NE) return;
    int b = blockIdx.y;

    int s = __ldg(esrc + e);
    int d = __ldg(edst + e);
    float w = __ldg(ew + e);

    const float4 v = *reinterpret_cast<const float4*>(
        g_h + ((size_t)b * NN + s) * NF + q * 4);
    float* ap = g_agg + ((size_t)b * NN + d) * NF + q * 4;

    asm volatile("red.global.add.v4.f32 [%0], {%1, %2, %3, %4};"
                 :: "l"(ap), "f"(v.x * w), "f"(v.y * w), "f"(v.z * w), "f"(v.w * w)
                 : "memory");
}

// ---------------------------------------------------------------------------
// Kernel 3: out[b,n,t] = relu( sum_f relu(agg[b,n,f] + b_gcn[f]) * w_dense[f,t]
//                              + b_dense[t] )
// One thread per (b,n); w_dense/biases staged in shared (broadcast reads).
// ---------------------------------------------------------------------------
__global__ void k3_out(const float* __restrict__ b_gcn, const float* __restrict__ w_dense,
                       const float* __restrict__ b_dense, float* __restrict__ out) {
    __shared__ float wd[NF * NT];
    __shared__ float bg[NF];
    __shared__ float bd[NT];
    int tid = threadIdx.x;
    for (int i = tid; i < NF * NT; i += 256) wd[i] = w_dense[i];
    if (tid < NF) bg[tid] = b_gcn[tid];
    if (tid < NT) bd[tid] = b_dense[tid];
    __syncthreads();

    int gid = blockIdx.x * 256 + tid;   // (b*NN + n)
    if (gid >= NB * NN) return;

    const float4* a4 = reinterpret_cast<const float4*>(g_agg + (size_t)gid * NF);

    float acc[NT];
#pragma unroll
    for (int t = 0; t < NT; ++t) acc[t] = 0.f;

#pragma unroll
    for (int f4 = 0; f4 < NF / 4; ++f4) {
        float4 v = a4[f4];
        float g0 = fmaxf(v.x + bg[f4 * 4 + 0], 0.f);
        float g1 = fmaxf(v.y + bg[f4 * 4 + 1], 0.f);
        float g2 = fmaxf(v.z + bg[f4 * 4 + 2], 0.f);
        float g3 = fmaxf(v.w + bg[f4 * 4 + 3], 0.f);
#pragma unroll
        for (int t = 0; t < NT; ++t) {
            acc[t] += g0 * wd[(f4 * 4 + 0) * NT + t];
            acc[t] += g1 * wd[(f4 * 4 + 1) * NT + t];
            acc[t] += g2 * wd[(f4 * 4 + 2) * NT + t];
            acc[t] += g3 * wd[(f4 * 4 + 3) * NT + t];
        }
    }

    float* op = out + (size_t)gid * NT;
#pragma unroll
    for (int t = 0; t < NT; ++t)
        op[t] = fmaxf(acc[t] + bd[t], 0.f);
}

// ---------------------------------------------------------------------------
extern "C" void kernel_launch(void* const* d_in, const int* in_sizes, int n_in,
                              void* d_out, int out_size) {
    const float* x       = (const float*)d_in[0];
    const float* ew      = (const float*)d_in[1];
    const float* w_gcn   = (const float*)d_in[2];
    const float* b_gcn   = (const float*)d_in[3];
    const float* w_dense = (const float*)d_in[4];
    const float* b_dense = (const float*)d_in[5];
    const int*   esrc    = (const int*)d_in[6];
    const int*   edst    = (const int*)d_in[7];
    float* out = (float*)d_out;

    k1_xw<<<dim3(NN / 4, NB), 256>>>(x, w_gcn);
    k2_scatter<<<dim3((NE * 16) / 256, NB), 256>>>(esrc, edst, ew);
    k3_out<<<(NB * NN + 255) / 256, 256>>>(b_gcn, w_dense, b_dense, out);
}

// round 2
// speedup vs baseline: 2.2460x; 2.2460x over previous
#include <cuda_runtime.h>

#define NB 8       // batch
#define NT 12      // time / feature-in dim
#define NN 20000   // nodes
#define NE 320000  // edges
#define NF 64      // gcn hidden

// Scratch (7.7 MB each; both L2-resident):
// g_xt : x transposed to [B, N, T] (node-major rows of 48B)
// g_agg: scatter accumulator, same layout (pre-GCN-weight aggregation)
__device__ __align__(128) float g_xt [(size_t)NB * NN * NT];
__device__ __align__(128) float g_agg[(size_t)NB * NN * NT];

// ---------------------------------------------------------------------------
// Kernel 1: xt[b,n,t] = x[b,t,n]; zero agg. One thread per node.
// Reads coalesced (12 strided 128B-per-warp loads), writes contiguous 48B rows.
// ---------------------------------------------------------------------------
__global__ void k1_transpose(const float* __restrict__ x) {
    int n = blockIdx.x * 256 + threadIdx.x;
    if (n >= NN) return;
    int b = blockIdx.y;

    const float* xb = x + (size_t)b * NT * NN + n;
    float a[NT];
#pragma unroll
    for (int t = 0; t < NT; ++t) a[t] = xb[(size_t)t * NN];

    float4* dst = reinterpret_cast<float4*>(g_xt  + ((size_t)b * NN + n) * NT);
    float4* za  = reinterpret_cast<float4*>(g_agg + ((size_t)b * NN + n) * NT);
#pragma unroll
    for (int q = 0; q < 3; ++q) {
        dst[q] = make_float4(a[4*q], a[4*q+1], a[4*q+2], a[4*q+3]);
        za[q]  = make_float4(0.f, 0.f, 0.f, 0.f);
    }
}

// ---------------------------------------------------------------------------
// Kernel 2: scatter in the T dimension (pre-weight): one thread per (b, e).
//   agg[b, dst, 0:12] += w_e * xt[b, src, 0:12]   via 3x red.global.add.v4.f32
// 48B per edge instead of 256B -> 5.3x less RED + gather traffic than R1.
// ---------------------------------------------------------------------------
__global__ void k2_scatter(const int* __restrict__ esrc, const int* __restrict__ edst,
                           const float* __restrict__ ew) {
    int e = blockIdx.x * 256 + threadIdx.x;
    if (e >= NE) return;
    int b = blockIdx.y;

    int s   = __ldg(esrc + e);
    int d   = __ldg(edst + e);
    float w = __ldg(ew + e);

    const float4* src = reinterpret_cast<const float4*>(g_xt + ((size_t)b * NN + s) * NT);
    float* ap = g_agg + ((size_t)b * NN + d) * NT;

#pragma unroll
    for (int q = 0; q < 3; ++q) {
        float4 v = src[q];
        asm volatile("red.global.add.v4.f32 [%0], {%1, %2, %3, %4};"
                     :: "l"(ap + q * 4),
                        "f"(v.x * w), "f"(v.y * w), "f"(v.z * w), "f"(v.w * w)
                     : "memory");
    }
}

// ---------------------------------------------------------------------------
// Kernel 3: fused epilogue, 2 nodes per thread (halves shared broadcast LDS):
//   g[f]   = relu( sum_t agg[b,n,t] * w_gcn[t,f] + b_gcn[f] )
//   out[t] = relu( sum_f g[f] * w_dense[f,t] + b_dense[t] )
// ---------------------------------------------------------------------------
__global__ void k3_out(const float* __restrict__ w_gcn, const float* __restrict__ b_gcn,
                       const float* __restrict__ w_dense, const float* __restrict__ b_dense,
                       float* __restrict__ out) {
    __shared__ float s_wg[NT * NF];   // [t][f]
    __shared__ float s_wd[NF * NT];   // [f][t]
    __shared__ float s_bg[NF];
    __shared__ float s_bd[NT];
    int tid = threadIdx.x;
    for (int i = tid; i < NT * NF; i += 256) s_wg[i] = w_gcn[i];
    for (int i = tid; i < NF * NT; i += 256) s_wd[i] = w_dense[i];
    if (tid < NF) s_bg[tid] = b_gcn[tid];
    if (tid < NT) s_bd[tid] = b_dense[tid];
    __syncthreads();

    int base = (blockIdx.x * 256 + tid) * 2;   // over B*NN (even)
    if (base >= NB * NN) return;

    float a0[NT], a1[NT], o0[NT], o1[NT];
    const float4* p0 = reinterpret_cast<const float4*>(g_agg + (size_t)base * NT);
    const float4* p1 = reinterpret_cast<const float4*>(g_agg + (size_t)(base + 1) * NT);
#pragma unroll
    for (int q = 0; q < 3; ++q) {
        float4 v0 = p0[q], v1 = p1[q];
        a0[4*q] = v0.x; a0[4*q+1] = v0.y; a0[4*q+2] = v0.z; a0[4*q+3] = v0.w;
        a1[4*q] = v1.x; a1[4*q+1] = v1.y; a1[4*q+2] = v1.z; a1[4*q+3] = v1.w;
    }
#pragma unroll
    for (int t = 0; t < NT; ++t) { o0[t] = 0.f; o1[t] = 0.f; }

#pragma unroll 4
    for (int f = 0; f < NF; ++f) {
        float g0 = s_bg[f], g1 = g0;
#pragma unroll
        for (int t = 0; t < NT; ++t) {
            float w = s_wg[t * NF + f];
            g0 += a0[t] * w;
            g1 += a1[t] * w;
        }
        g0 = fmaxf(g0, 0.f);
        g1 = fmaxf(g1, 0.f);
#pragma unroll
        for (int t = 0; t < NT; ++t) {
            float w = s_wd[f * NT + t];
            o0[t] += g0 * w;
            o1[t] += g1 * w;
        }
    }

    float* op0 = out + (size_t)base * NT;
    float* op1 = out + (size_t)(base + 1) * NT;
#pragma unroll
    for (int t = 0; t < NT; ++t) {
        op0[t] = fmaxf(o0[t] + s_bd[t], 0.f);
        op1[t] = fmaxf(o1[t] + s_bd[t], 0.f);
    }
}

// ---------------------------------------------------------------------------
extern "C" void kernel_launch(void* const* d_in, const int* in_sizes, int n_in,
                              void* d_out, int out_size) {
    const float* x       = (const float*)d_in[0];
    const float* ew      = (const float*)d_in[1];
    const float* w_gcn   = (const float*)d_in[2];
    const float* b_gcn   = (const float*)d_in[3];
    const float* w_dense = (const float*)d_in[4];
    const float* b_dense = (const float*)d_in[5];
    const int*   esrc    = (const int*)d_in[6];
    const int*   edst    = (const int*)d_in[7];
    float* out = (float*)d_out;

    k1_transpose<<<dim3((NN + 255) / 256, NB), 256>>>(x);
    k2_scatter<<<dim3((NE + 255) / 256, NB), 256>>>(esrc, edst, ew);
    k3_out<<<(NB * NN / 2 + 255) / 256, 256>>>(w_gcn, b_gcn, w_dense, b_dense, out);
}

// round 3
// speedup vs baseline: 2.6770x; 1.1919x over previous
#include <cuda_runtime.h>

#define NB 8       // batch
#define NT 12      // time / feature-in dim
#define NN 20000   // nodes
#define NE 320000  // edges
#define NF 64      // gcn hidden
#define NBT (NB * NT)   // 96 floats per node row

// Scratch (all __device__ globals; ~18 MB total, L2-resident):
__device__ __align__(128) float g_xt [(size_t)NN * NBT];   // [n][b*12+t]
__device__ __align__(128) float g_agg[(size_t)NN * NBT];   // same layout
__device__ int   g_deg[NN];
__device__ int   g_cursor[NN];
__device__ int   g_rowstart[NN + 1];
__device__ int   g_esrc2[NE];   // CSR-ordered (by dst) src ids
__device__ float g_ew2[NE];     // CSR-ordered edge weights

// ---------------------------------------------------------------------------
// k1: xt[n][b*12+t] = x[b,t,n]. One thread per (b,n); reads coalesced over n.
// ---------------------------------------------------------------------------
__global__ void k1_transpose(const float* __restrict__ x) {
    int n = blockIdx.x * 256 + threadIdx.x;
    if (n >= NN) return;
    int b = blockIdx.y;

    const float* xb = x + (size_t)b * NT * NN + n;
    float a[NT];
#pragma unroll
    for (int t = 0; t < NT; ++t) a[t] = xb[(size_t)t * NN];

    float4* dst = reinterpret_cast<float4*>(g_xt + (size_t)n * NBT + b * NT);
#pragma unroll
    for (int q = 0; q < 3; ++q)
        dst[q] = make_float4(a[4*q], a[4*q+1], a[4*q+2], a[4*q+3]);
}

// ---------------------------------------------------------------------------
// CSR build: zero -> histogram -> scan -> fill
// ---------------------------------------------------------------------------
__global__ void k_zero() {
    int i = blockIdx.x * 256 + threadIdx.x;
    if (i < NN) { g_deg[i] = 0; g_cursor[i] = 0; }
}

__global__ void k_hist(const int* __restrict__ edst) {
    int e = blockIdx.x * 256 + threadIdx.x;
    if (e < NE) atomicAdd(&g_deg[edst[e]], 1);
}

// Single-block exclusive scan of g_deg -> g_rowstart. 1024 threads x 20 elems.
__global__ void k_scan() {
    __shared__ int s[1024];
    int tid = threadIdx.x;
    const int CH = (NN + 1023) / 1024;     // 20
    int lo = tid * CH;
    int hi = lo + CH; if (hi > NN) hi = NN;

    int sum = 0;
    for (int i = lo; i < hi; ++i) sum += g_deg[i];
    s[tid] = sum;
    __syncthreads();
    // inclusive Hillis-Steele scan
    for (int off = 1; off < 1024; off <<= 1) {
        int v = (tid >= off) ? s[tid - off] : 0;
        __syncthreads();
        s[tid] += v;
        __syncthreads();
    }
    int run = (tid == 0) ? 0 : s[tid - 1];
    for (int i = lo; i < hi; ++i) { g_rowstart[i] = run; run += g_deg[i]; }
    if (tid == 1023) g_rowstart[NN] = s[1023];
}

__global__ void k_fill(const int* __restrict__ esrc, const int* __restrict__ edst,
                       const float* __restrict__ ew) {
    int e = blockIdx.x * 256 + threadIdx.x;
    if (e >= NE) return;
    int d = edst[e];
    int pos = g_rowstart[d] + atomicAdd(&g_cursor[d], 1);
    g_esrc2[pos] = esrc[e];
    g_ew2[pos]   = ew[e];
}

// ---------------------------------------------------------------------------
// k2: warp-per-node gather, NO atomics. Each edge: 3 coalesced 128B loads of
// xt[src] (all 8 batches at once), 3 FMA/lane. One 384B store per node.
// ---------------------------------------------------------------------------
__global__ void k2_gather() {
    int node = blockIdx.x * 8 + (threadIdx.x >> 5);
    int lane = threadIdx.x & 31;
    if (node >= NN) return;

    int i   = g_rowstart[node];
    int end = g_rowstart[node + 1];

    float a0 = 0.f, a1 = 0.f, a2 = 0.f;

    for (; i + 1 < end; i += 2) {
        int   s0 = g_esrc2[i],   s1 = g_esrc2[i + 1];
        float w0 = g_ew2[i],     w1 = g_ew2[i + 1];
        const float* p0 = g_xt + (size_t)s0 * NBT;
        const float* p1 = g_xt + (size_t)s1 * NBT;
        float v00 = p0[lane], v01 = p0[lane + 32], v02 = p0[lane + 64];
        float v10 = p1[lane], v11 = p1[lane + 32], v12 = p1[lane + 64];
        a0 += w0 * v00; a1 += w0 * v01; a2 += w0 * v02;
        a0 += w1 * v10; a1 += w1 * v11; a2 += w1 * v12;
    }
    if (i < end) {
        int   s0 = g_esrc2[i];
        float w0 = g_ew2[i];
        const float* p0 = g_xt + (size_t)s0 * NBT;
        a0 += w0 * p0[lane]; a1 += w0 * p0[lane + 32]; a2 += w0 * p0[lane + 64];
    }

    float* ap = g_agg + (size_t)node * NBT;
    ap[lane] = a0; ap[lane + 32] = a1; ap[lane + 64] = a2;
}

// ---------------------------------------------------------------------------
// k3: fused epilogue. One thread per (b,n):
//   g[f]   = relu( sum_t agg[n][b*12+t] * w_gcn[t,f] + b_gcn[f] )
//   out[b,n,t] = relu( sum_f g[f] * w_dense[f,t] + b_dense[t] )
// ---------------------------------------------------------------------------
__global__ void k3_out(const float* __restrict__ w_gcn, const float* __restrict__ b_gcn,
                       const float* __restrict__ w_dense, const float* __restrict__ b_dense,
                       float* __restrict__ out) {
    __shared__ float s_wg[NT * NF];   // [t][f]
    __shared__ float s_wd[NF * NT];   // [f][t]
    __shared__ float s_bg[NF];
    __shared__ float s_bd[NT];
    int tid = threadIdx.x;
    for (int i = tid; i < NT * NF; i += 256) s_wg[i] = w_gcn[i];
    for (int i = tid; i < NF * NT; i += 256) s_wd[i] = w_dense[i];
    if (tid < NF) s_bg[tid] = b_gcn[tid];
    if (tid < NT) s_bd[tid] = b_dense[tid];
    __syncthreads();

    int gid = blockIdx.x * 256 + tid;       // b*NN + n
    if (gid >= NB * NN) return;
    int b = gid / NN;
    int n = gid - b * NN;

    float a[NT], o[NT];
    const float4* p = reinterpret_cast<const float4*>(g_agg + (size_t)n * NBT + b * NT);
#pragma unroll
    for (int q = 0; q < 3; ++q) {
        float4 v = p[q];
        a[4*q] = v.x; a[4*q+1] = v.y; a[4*q+2] = v.z; a[4*q+3] = v.w;
    }
#pragma unroll
    for (int t = 0; t < NT; ++t) o[t] = 0.f;

#pragma unroll 4
    for (int f = 0; f < NF; ++f) {
        float g = s_bg[f];
#pragma unroll
        for (int t = 0; t < NT; ++t) g += a[t] * s_wg[t * NF + f];
        g = fmaxf(g, 0.f);
#pragma unroll
        for (int t = 0; t < NT; ++t) o[t] += g * s_wd[f * NT + t];
    }

    float* op = out + (size_t)gid * NT;
#pragma unroll
    for (int t = 0; t < NT; ++t)
        op[t] = fmaxf(o[t] + s_bd[t], 0.f);
}

// ---------------------------------------------------------------------------
extern "C" void kernel_launch(void* const* d_in, const int* in_sizes, int n_in,
                              void* d_out, int out_size) {
    const float* x       = (const float*)d_in[0];
    const float* ew      = (const float*)d_in[1];
    const float* w_gcn   = (const float*)d_in[2];
    const float* b_gcn   = (const float*)d_in[3];
    const float* w_dense = (const float*)d_in[4];
    const float* b_dense = (const float*)d_in[5];
    const int*   esrc    = (const int*)d_in[6];
    const int*   edst    = (const int*)d_in[7];
    float* out = (float*)d_out;

    k1_transpose<<<dim3((NN + 255) / 256, NB), 256>>>(x);
    k_zero<<<(NN + 255) / 256, 256>>>();
    k_hist<<<(NE + 255) / 256, 256>>>(edst);
    k_scan<<<1, 1024>>>();
    k_fill<<<(NE + 255) / 256, 256>>>(esrc, edst, ew);
    k2_gather<<<(NN + 7) / 8, 256>>>();
    k3_out<<<(NB * NN + 255) / 256, 256>>>(w_gcn, b_gcn, w_dense, b_dense, out);
}

// round 4
// speedup vs baseline: 3.1102x; 1.1618x over previous
#include <cuda_runtime.h>

#define NB 8       // batch
#define NT 12      // time / feature-in dim
#define NN 20000   // nodes
#define NE 320000  // edges
#define NF 64      // gcn hidden
#define NBT (NB * NT)   // 96 floats per node row
#define CAP 64          // bucket capacity per node (Poisson(16); P(>64) ~ 1e-20)

// Scratch (__device__ globals; ~18 MB, L2-resident)
__device__ __align__(128) float g_xt[(size_t)NN * NBT];  // [n][b*12+t]
__device__ __align__(128) int2  g_bkt[(size_t)NN * CAP]; // {src, w-as-int} per in-edge
__device__ int g_cnt[NN];

// ---------------------------------------------------------------------------
// k1: transpose x[B,T,N] -> g_xt[N][B*T] via smem staging (coalesced both ways)
//     + zero the bucket counters. One block per 32 nodes.
// ---------------------------------------------------------------------------
__global__ void k1_transpose(const float* __restrict__ x) {
    __shared__ float s[NB * NT * 32];   // [bt][nloc] : 3072 floats
    int tid = threadIdx.x;
    int n0 = blockIdx.x * 32;

    if (tid < 32) g_cnt[n0 + tid] = 0;

#pragma unroll
    for (int k = 0; k < 12; ++k) {
        int i = tid + 256 * k;          // 0..3071
        int bt = i >> 5, nl = i & 31;
        s[i] = x[(size_t)bt * NN + n0 + nl];
    }
    __syncthreads();

    float4* dst = reinterpret_cast<float4*>(g_xt + (size_t)n0 * NBT);
#pragma unroll
    for (int k = 0; k < 3; ++k) {
        int o4 = tid + 256 * k;         // float4 index 0..767 (contiguous stores)
        int o = o4 * 4;
        int n = o / NBT, r = o % NBT;   // r = b*12 + t, t in {0,4,8}
        int si = r * 32 + n;            // s[(b*12+t)*32 + n]; t+1 -> +32
        dst[o4] = make_float4(s[si], s[si + 32], s[si + 64], s[si + 96]);
    }
}

// ---------------------------------------------------------------------------
// k_fill: bucket edges by destination. One thread per edge, one 8B store.
// ---------------------------------------------------------------------------
__global__ void k_fill(const int* __restrict__ esrc, const int* __restrict__ edst,
                       const float* __restrict__ ew) {
    int e = blockIdx.x * 256 + threadIdx.x;
    if (e >= NE) return;
    int d = edst[e];
    int pos = atomicAdd(&g_cnt[d], 1);
    if (pos < CAP)
        g_bkt[(size_t)d * CAP + pos] = make_int2(esrc[e], __float_as_int(ew[e]));
}

// ---------------------------------------------------------------------------
// k2: fused gather + epilogue. One warp per destination node.
//   phase 1: agg[0:96] = sum_edges w_e * xt[src]   (3 coalesced 128B loads/edge)
//   phase 2: g[b][f] = relu(agg[b,:] @ w_gcn + bg)
//   phase 3: out[b,node,t] = relu(g[b,:] @ w_dense + bd)
// ---------------------------------------------------------------------------
__global__ void __launch_bounds__(256) k2_fused(
        const int* __restrict__ esrc, const int* __restrict__ edst,
        const float* __restrict__ ew,
        const float* __restrict__ w_gcn, const float* __restrict__ b_gcn,
        const float* __restrict__ w_dense, const float* __restrict__ b_dense,
        float* __restrict__ out) {
    __shared__ float s_wg[NT * NF];        // [t][f]
    __shared__ float s_wd[NF * NT];        // [f][t]
    __shared__ float s_bg[NF];
    __shared__ float s_bd[NT];
    __shared__ float s_agg[8][NBT];        // per-warp agg
    __shared__ float s_g[8][NB][NF + 1];   // per-warp gcn activations (pad 65)

    int tid = threadIdx.x;
    int w = tid >> 5, lane = tid & 31;

    for (int i = tid; i < NT * NF; i += 256) { s_wg[i] = w_gcn[i]; s_wd[i] = w_dense[i]; }
    if (tid < NF) s_bg[tid] = b_gcn[tid];
    if (tid < NT) s_bd[tid] = b_dense[tid];
    __syncthreads();

    int node = blockIdx.x * 8 + w;         // 2500*8 == NN exactly
    int cnt = g_cnt[node];

    float a0 = 0.f, a1 = 0.f, a2 = 0.f;
    if (cnt <= CAP) {
        const int2* bp = g_bkt + (size_t)node * CAP;
        for (int base = 0; base < cnt; base += 32) {
            int m = cnt - base; if (m > 32) m = 32;
            int2 slot = (lane < m) ? bp[base + lane] : make_int2(0, 0);
            for (int j = 0; j < m; ++j) {
                int   s  = __shfl_sync(0xffffffffu, slot.x, j);
                float wt = __int_as_float(__shfl_sync(0xffffffffu, slot.y, j));
                const float* p = g_xt + (size_t)s * NBT;
                a0 += wt * p[lane];
                a1 += wt * p[lane + 32];
                a2 += wt * p[lane + 64];
            }
        }
    } else {
        // Overflow fallback (never triggers for Poisson(16) degrees; keeps
        // the kernel unconditionally correct): rescan the full edge list.
        for (int e = 0; e < NE; ++e) {
            if (__ldg(edst + e) == node) {
                float wt = __ldg(ew + e);
                const float* p = g_xt + (size_t)__ldg(esrc + e) * NBT;
                a0 += wt * p[lane];
                a1 += wt * p[lane + 32];
                a2 += wt * p[lane + 64];
            }
        }
    }

    s_agg[w][lane] = a0; s_agg[w][lane + 32] = a1; s_agg[w][lane + 64] = a2;
    __syncwarp();

    // phase 2: 512 g-values per node, 16 per lane. b is uniform across the
    // warp for each i (broadcast s_agg reads), f consecutive (no conflicts).
#pragma unroll
    for (int i = 0; i < 16; ++i) {
        int idx = lane + 32 * i;
        int b = idx >> 6, f = idx & 63;
        float g = s_bg[f];
#pragma unroll
        for (int t = 0; t < NT; ++t)
            g += s_agg[w][b * NT + t] * s_wg[t * NF + f];
        s_g[w][b][f] = fmaxf(g, 0.f);
    }
    __syncwarp();

    // phase 3: 96 outputs per node, 3 per lane.
#pragma unroll
    for (int j = 0; j < 3; ++j) {
        int idx = lane + 32 * j;
        int b = idx / NT, t = idx - b * NT;
        float o = s_bd[t];
#pragma unroll
        for (int f = 0; f < NF; ++f)
            o += s_g[w][b][f] * s_wd[f * NT + t];
        out[((size_t)b * NN + node) * NT + t] = fmaxf(o, 0.f);
    }
}

// ---------------------------------------------------------------------------
extern "C" void kernel_launch(void* const* d_in, const int* in_sizes, int n_in,
                              void* d_out, int out_size) {
    const float* x       = (const float*)d_in[0];
    const float* ew      = (const float*)d_in[1];
    const float* w_gcn   = (const float*)d_in[2];
    const float* b_gcn   = (const float*)d_in[3];
    const float* w_dense = (const float*)d_in[4];
    const float* b_dense = (const float*)d_in[5];
    const int*   esrc    = (const int*)d_in[6];
    const int*   edst    = (const int*)d_in[7];
    float* out = (float*)d_out;

    k1_transpose<<<NN / 32, 256>>>(x);
    k_fill<<<(NE + 255) / 256, 256>>>(esrc, edst, ew);
    k2_fused<<<NN / 8, 256>>>(esrc, edst, ew, w_gcn, b_gcn, w_dense, b_dense, out);
}